// round 1
// baseline (speedup 1.0000x reference)
#include <cuda_runtime.h>
#include <cstdint>

// TopologyTracker: 64x64 histogram of (prev, curr) transitions over 16.7M events.
// Output layout (float32): [0..4095] = transitions + counts, [4096] = total + N.

#define NUM_TILES 64
#define NUM_BINS  (NUM_TILES * NUM_TILES)   // 4096

// ---------------------------------------------------------------------------
// Kernel 1: seed output with the incoming transitions matrix + updated total.
// ---------------------------------------------------------------------------
__global__ void tt_init_out(const float* __restrict__ trans_in,
                            const float* __restrict__ total_in,
                            float* __restrict__ out,
                            int out_size,
                            float n_events)
{
    int i = blockIdx.x * blockDim.x + threadIdx.x;
    if (i < NUM_BINS && i < out_size) {
        out[i] = trans_in[i];
    }
    if (i == NUM_BINS && i < out_size) {
        out[NUM_BINS] = total_in[0] + n_events;
    }
}

// ---------------------------------------------------------------------------
// Kernel 2: per-CTA shared histogram, int4-vectorized event stream,
// one float-atomic flush per (block, bin).
// ---------------------------------------------------------------------------
__global__ void __launch_bounds__(512, 2)
tt_hist(const int* __restrict__ prev,
        const int* __restrict__ curr,
        float* __restrict__ out,
        int n)
{
    __shared__ int h[NUM_BINS];

    // Zero shared histogram.
    #pragma unroll
    for (int i = threadIdx.x; i < NUM_BINS; i += 512) {
        h[i] = 0;
    }
    __syncthreads();

    const int tid    = blockIdx.x * 512 + threadIdx.x;
    const int stride = gridDim.x * 512;

    // Vectorized main body: 4 events per int4 pair.
    const int n4 = n >> 2;
    const int4* __restrict__ p4 = reinterpret_cast<const int4*>(prev);
    const int4* __restrict__ c4 = reinterpret_cast<const int4*>(curr);

    for (int i = tid; i < n4; i += stride) {
        int4 p = p4[i];
        int4 c = c4[i];
        atomicAdd(&h[(p.x << 6) + c.x], 1);
        atomicAdd(&h[(p.y << 6) + c.y], 1);
        atomicAdd(&h[(p.z << 6) + c.z], 1);
        atomicAdd(&h[(p.w << 6) + c.w], 1);
    }

    // Scalar tail (N = 16777216 is divisible by 4; kept for safety).
    for (int i = (n4 << 2) + tid; i < n; i += stride) {
        atomicAdd(&h[(prev[i] << 6) + curr[i]], 1);
    }

    __syncthreads();

    // Flush: one float atomic per non-empty bin per block.
    #pragma unroll
    for (int i = threadIdx.x; i < NUM_BINS; i += 512) {
        int v = h[i];
        if (v != 0) {
            atomicAdd(&out[i], (float)v);
        }
    }
}

// ---------------------------------------------------------------------------
// Launcher
// ---------------------------------------------------------------------------
extern "C" void kernel_launch(void* const* d_in, const int* in_sizes, int n_in,
                              void* d_out, int out_size)
{
    const int*   prev     = (const int*)  d_in[0];
    const int*   curr     = (const int*)  d_in[1];
    const float* trans_in = (const float*)d_in[2];
    const float* total_in = (const float*)d_in[3];
    float*       out      = (float*)d_out;

    const int n = in_sizes[0];

    // Seed output: transitions copy + total scalar.
    {
        int threads = 256;
        int blocks  = (NUM_BINS + 1 + threads - 1) / threads;
        tt_init_out<<<blocks, threads>>>(trans_in, total_in, out, out_size, (float)n);
    }

    // Histogram accumulation.
    {
        const int threads = 512;
        const int blocks  = 296;  // 2 CTAs/SM * 148 SMs
        tt_hist<<<blocks, threads>>>(prev, curr, out, n);
    }
}

// round 2
// speedup vs baseline: 1.0538x; 1.0538x over previous
#include <cuda_runtime.h>
#include <cstdint>

// TopologyTracker: 64x64 histogram of (prev, curr) transitions over 16.7M events.
// Output layout (float32): [0..4095] = transitions + counts, [4096] = total + N.

#define NUM_TILES 64
#define NUM_BINS  (NUM_TILES * NUM_TILES)   // 4096

// ---------------------------------------------------------------------------
// Kernel 1: seed output with the incoming transitions matrix + updated total.
// ---------------------------------------------------------------------------
__global__ void tt_init_out(const float* __restrict__ trans_in,
                            const float* __restrict__ total_in,
                            float* __restrict__ out,
                            int out_size,
                            float n_events)
{
    int i = blockIdx.x * blockDim.x + threadIdx.x;
    if (i < NUM_BINS && i < out_size) {
        out[i] = trans_in[i];
    }
    if (i == NUM_BINS && i < out_size) {
        out[NUM_BINS] = total_in[0] + n_events;
    }
}

// ---------------------------------------------------------------------------
// Kernel 2: per-CTA shared histogram. 4 CTAs/SM for load-latency hiding,
// 8 events per thread-iteration (4 front-batched int4 streaming loads),
// one float-atomic flush per (block, bin).
// ---------------------------------------------------------------------------
__global__ void __launch_bounds__(512, 4)
tt_hist(const int* __restrict__ prev,
        const int* __restrict__ curr,
        float* __restrict__ out,
        int n)
{
    __shared__ int h[NUM_BINS];

    // Zero shared histogram.
    #pragma unroll
    for (int i = threadIdx.x; i < NUM_BINS; i += 512) {
        h[i] = 0;
    }
    __syncthreads();

    const int tid    = blockIdx.x * 512 + threadIdx.x;
    const int stride = gridDim.x * 512;

    const int4* __restrict__ p4 = reinterpret_cast<const int4*>(prev);
    const int4* __restrict__ c4 = reinterpret_cast<const int4*>(curr);

    // Main body: 8 events per iteration. Each thread owns two adjacent int4s
    // in each stream (32B per array) -> warp covers 1KB contiguous per array.
    const int n8 = n >> 3;   // groups of 8 events
    for (int i = tid; i < n8; i += stride) {
        // Front-batch 4 independent 16B streaming loads (single-use data).
        int4 pa = __ldcs(&p4[2 * i]);
        int4 pb = __ldcs(&p4[2 * i + 1]);
        int4 ca = __ldcs(&c4[2 * i]);
        int4 cb = __ldcs(&c4[2 * i + 1]);

        atomicAdd(&h[(pa.x << 6) + ca.x], 1);
        atomicAdd(&h[(pa.y << 6) + ca.y], 1);
        atomicAdd(&h[(pa.z << 6) + ca.z], 1);
        atomicAdd(&h[(pa.w << 6) + ca.w], 1);
        atomicAdd(&h[(pb.x << 6) + cb.x], 1);
        atomicAdd(&h[(pb.y << 6) + cb.y], 1);
        atomicAdd(&h[(pb.z << 6) + cb.z], 1);
        atomicAdd(&h[(pb.w << 6) + cb.w], 1);
    }

    // Scalar tail (N = 16777216 is divisible by 8; kept for safety).
    for (int i = (n8 << 3) + tid; i < n; i += stride) {
        atomicAdd(&h[(prev[i] << 6) + curr[i]], 1);
    }

    __syncthreads();

    // Flush: one float atomic per non-empty bin per block.
    #pragma unroll
    for (int i = threadIdx.x; i < NUM_BINS; i += 512) {
        int v = h[i];
        if (v != 0) {
            atomicAdd(&out[i], (float)v);
        }
    }
}

// ---------------------------------------------------------------------------
// Launcher
// ---------------------------------------------------------------------------
extern "C" void kernel_launch(void* const* d_in, const int* in_sizes, int n_in,
                              void* d_out, int out_size)
{
    const int*   prev     = (const int*)  d_in[0];
    const int*   curr     = (const int*)  d_in[1];
    const float* trans_in = (const float*)d_in[2];
    const float* total_in = (const float*)d_in[3];
    float*       out      = (float*)d_out;

    const int n = in_sizes[0];

    // Seed output: transitions copy + total scalar.
    {
        int threads = 256;
        int blocks  = (NUM_BINS + 1 + threads - 1) / threads;
        tt_init_out<<<blocks, threads>>>(trans_in, total_in, out, out_size, (float)n);
    }

    // Histogram accumulation: 4 CTAs/SM * 148 SMs.
    {
        const int threads = 512;
        const int blocks  = 592;
        tt_hist<<<blocks, threads>>>(prev, curr, out, n);
    }
}